// round 13
// baseline (speedup 1.0000x reference)
#include <cuda_runtime.h>
#include <cstdint>

// Problem constants (fixed by the reference)
#define B_ 32
#define S_ 512
#define P_ 8
#define K_ 256
#define D_ 64
#define NROWS (B_ * S_ * P_)   // 131072 rows of K=256 logits each

#define FULL 0xffffffffu
#define NEG_INF __int_as_float(0xff800000)
#define LN2F 0.69314718055994530942f
#define TINYF 1.17549435e-38f

__device__ __forceinline__ uint32_t rotl32(uint32_t x, int r) {
    return __funnelshift_l(x, x, r);
}
__device__ __forceinline__ float lg2a(float x) {
    float r;
    asm("lg2.approx.f32 %0, %1;" : "=f"(r) : "f"(x));
    return r;
}

// ---------------------------------------------------------------------------
// JAX threefry2x32, partitionable mode, key (0, 42); counter = (0, i).
// Draw = x0 ^ x1. ks = (0, 42, 0x1BD11BDA^42). Plain SHF/LOP3/IADD core:
// R5/R8/R11/R12 all measured that relocating or widening ops on this serial
// chain loses more in issue/latency than it saves in alu-pipe slots.
// ---------------------------------------------------------------------------
__device__ __forceinline__ uint32_t threefry_bits(uint32_t i) {
    const uint32_t KS1 = 42u;
    const uint32_t KS2 = 0x1BD11BDAu ^ 42u;
#define RND(r)             { x0 += x1; x1 = rotl32(x1, (r)) ^ x0; }
#define RNDK(r, kx0, kx1)  { x1 += (kx1); x0 += x1 + (kx0); x1 = rotl32(x1, (r)) ^ x0; }
    uint32_t x1 = i + KS1;
    uint32_t x0 = x1;                          // round 1 add: x0 = 0 + x1
    x1 = rotl32(x1, 13) ^ x0;
    RND(15) RND(26) RND(6)
    RNDK(17, KS1, KS2 + 1u)
    RND(29) RND(16) RND(24)
    RNDK(13, KS2, 2u)                          // ks0 = 0
    RND(15) RND(26) RND(6)
    RNDK(17, 0u, KS1 + 3u)
    RND(29) RND(16) RND(24)
    RNDK(13, KS1, KS2 + 4u)
    RND(15) RND(26) RND(6)
    x0 += KS2;  x1 += 5u;
#undef RND
#undef RNDK
    return x0 ^ x1;
}

// Exact path: bit-identical to the reference fp32 computation (accurate logf).
// (f + TINYF == fmaxf(f, tiny) for every representable f in {0} U [2^-23, 1).)
__device__ __forceinline__ float exact_score(const float* __restrict__ erow,
                                             uint32_t row_base, int k) {
    uint32_t bits = threefry_bits(row_base + (uint32_t)k);
    float f = __uint_as_float((bits >> 9) | 0x3f800000u) - 1.0f;  // u in [0,1)
    float u = f + TINYF;
    float g = -logf(-logf(u));
    return __ldg(erow + k) + g;
}

// ---------------------------------------------------------------------------
// One warp per (b, s, p) row. Fast scores via lg2.approx (MUFU pipe):
//   s_j = e_j - ln2 * lg2a(-lg2a(u_j))  ==  (exact_j + const-shift) +- ~2.5e-5
// Fast path valid iff exactly one element lies in [smax - 4e-4, smax]:
//   ballot of lanes with a band element is a power of two AND the owning
//   lane's band mask is a power of two. Else (~50 rows in 131072) rerun the
//   bit-exact accurate-logf path on the band (rolled loop, cold code).
// ---------------------------------------------------------------------------
__global__ void __launch_bounds__(256, 8) symbolic_gumbel_kernel(
    const int*   __restrict__ inputs,       // [B, S] int32
    const float* __restrict__ pattern_map,  // [N_CAT, P, K]
    const float* __restrict__ symbols,      // [K, D]
    float*       __restrict__ out)          // [B, S, P*D]
{
    const int warp = (blockIdx.x * blockDim.x + threadIdx.x) >> 5;
    const int lane = threadIdx.x & 31;

    const int row = warp;                    // grid covers exactly NROWS warps
    const int bs  = row >> 3;
    const int p   = row & 7;
    const int cat = __ldg(&inputs[bs]);

    const float* erow = pattern_map + ((size_t)cat * P_ + p) * K_;
    const uint32_t row_base = (uint32_t)row * (uint32_t)K_;
    const uint32_t base = row_base + (uint32_t)(lane * 8);

    const float4* e4 = reinterpret_cast<const float4*>(erow + lane * 8);
    float4 ea = __ldg(&e4[0]);
    float4 eb = __ldg(&e4[1]);
    float e[8] = {ea.x, ea.y, ea.z, ea.w, eb.x, eb.y, eb.z, eb.w};

    // ---- Pass 1: fast scores ----
    float s[8];
#pragma unroll
    for (int j = 0; j < 8; j++) {
        uint32_t bits = threefry_bits(base + (uint32_t)j);
        float f  = __uint_as_float((bits >> 9) | 0x3f800000u) - 1.0f;  // u in [0,1)
        float u  = f + TINYF;               // == fmaxf(f, tiny), on the fma pipe
        float l1 = lg2a(u);                 // < 0
        float t  = lg2a(-l1);               // neg folds into MUFU src modifier
        s[j] = fmaf(t, -LN2F, e[j]);        // e - ln2*lg2(-lg2 u)
    }

    // Lane-local max (tree) then warp REDUX via monotone uint mapping.
    float m0 = fmaxf(s[0], s[1]), m1 = fmaxf(s[2], s[3]);
    float m2 = fmaxf(s[4], s[5]), m3 = fmaxf(s[6], s[7]);
    float lmax = fmaxf(fmaxf(m0, m1), fmaxf(m2, m3));
    uint32_t ub = __float_as_uint(lmax);
    ub ^= (uint32_t)((int32_t)ub >> 31) | 0x80000000u;     // order-preserving map
    uint32_t um = __reduce_max_sync(FULL, ub);
    um ^= ~(uint32_t)((int32_t)um >> 31) | 0x80000000u;    // inverse map
    const float smax = __uint_as_float(um);

    // ---- Candidate band as a bitmask ----
    const float thr = smax - 4e-4f;
    uint32_t mask = 0;
#pragma unroll
    for (int j = 0; j < 8; j++)
        if (s[j] >= thr) mask |= (1u << j);

    // ball is never 0 (smax's own element is in the band).
    const unsigned ball  = __ballot_sync(FULL, mask != 0);
    const int      owner = __ffs(ball) - 1;
    const uint32_t om    = __shfl_sync(FULL, mask, owner);
    // Exactly one band element <=> one lane in band AND that lane has one bit.
    const bool unique = ((ball & (ball - 1)) == 0u) && ((om & (om - 1)) == 0u);

    int bestk;
    if (unique) {
        bestk = owner * 8 + (__ffs(om) - 1);   // computed by all lanes, no shfl
    } else {
        // Rare (~50/131072 rows): exact (reference-identical) scores on the
        // band. Rolled loop keeps the cold code small (I$ friendly). Ascending
        // k with strict '>' preserves jnp.argmax first-index tie-break.
        float bestx = NEG_INF;
        bestk = K_;
        for (int j = 0; j < 8; j++) {           // NOT unrolled: cold path
            int   k = lane * 8 + j;
            float x = NEG_INF;
            if ((mask >> j) & 1u) x = exact_score(erow, row_base, k);
            if (x > bestx) { bestx = x; bestk = k; }
        }
#pragma unroll
        for (int off = 16; off > 0; off >>= 1) {
            float ob = __shfl_xor_sync(FULL, bestx, off);
            int   ok = __shfl_xor_sync(FULL, bestk, off);
            if (ob > bestx || (ob == bestx && ok < bestk)) { bestx = ob; bestk = ok; }
        }
    }

    // Copy symbols[bestk, :] (64 floats = 256B) to out[row, :], 2 floats/lane
    const float2* srow = reinterpret_cast<const float2*>(symbols + (size_t)bestk * D_);
    float2 val = __ldg(&srow[lane]);
    float2* orow = reinterpret_cast<float2*>(out + (size_t)row * D_);
    orow[lane] = val;
}

extern "C" void kernel_launch(void* const* d_in, const int* in_sizes, int n_in,
                              void* d_out, int out_size) {
    const int*   inputs      = (const int*)  d_in[0];  // [32, 512] int32
    const float* pattern_map = (const float*)d_in[1];  // [50000, 8, 256]
    const float* symbols     = (const float*)d_in[2];  // [256, 64]
    // d_in[3] = tau (== 1.0, positive): argmax invariant; straight-through
    // weights are one-hot to fp32 rounding, so tau is unused.
    float* out = (float*)d_out;                        // [32, 512, 512]

    const int threads = 256;                 // 8 warps -> 8 rows per block
    const int blocks  = NROWS / 8;           // 16384
    symbolic_gumbel_kernel<<<blocks, threads>>>(inputs, pattern_map, symbols, out);
}

// round 14
// speedup vs baseline: 1.0970x; 1.0970x over previous
#include <cuda_runtime.h>
#include <cstdint>

// Problem constants (fixed by the reference)
#define B_ 32
#define S_ 512
#define P_ 8
#define K_ 256
#define D_ 64
#define NROWS (B_ * S_ * P_)   // 131072 rows of K=256 logits each

#define FULL 0xffffffffu
#define NEG_INF __int_as_float(0xff800000)
#define LN2F 0.69314718055994530942f
#define TINYF 1.17549435e-38f

__device__ __forceinline__ uint32_t rotl32(uint32_t x, int r) {
    return __funnelshift_l(x, x, r);
}
__device__ __forceinline__ float lg2a(float x) {
    float r;
    asm("lg2.approx.f32 %0, %1;" : "=f"(r) : "f"(x));
    return r;
}

// ---------------------------------------------------------------------------
// JAX threefry2x32, partitionable mode, key (0, 42); counter = (0, i).
// Draw = x0 ^ x1. ks = (0, 42, 0x1BD11BDA^42). Plain SHF/LOP3/IADD core —
// R5/R8/R11/R12 measured that relocating or widening ops on this serial
// chain loses more in issue/latency than it saves in alu-pipe slots.
// ---------------------------------------------------------------------------
__device__ __forceinline__ uint32_t threefry_bits(uint32_t i) {
    const uint32_t KS1 = 42u;
    const uint32_t KS2 = 0x1BD11BDAu ^ 42u;
    uint32_t x1 = i + KS1;
    uint32_t x0 = x1;                  // round 1: x0 = 0 + x1
    x1 = rotl32(x1, 13) ^ x0;
#define RND(r) { x0 += x1; x1 = rotl32(x1, (r)) ^ x0; }
    RND(15) RND(26) RND(6)
    x0 += KS1;  x1 += KS2 + 1u;
    RND(17) RND(29) RND(16) RND(24)
    x0 += KS2;  x1 += 2u;              // ks0 = 0
    RND(13) RND(15) RND(26) RND(6)
    /* x0 += ks0 == 0 */ x1 += KS1 + 3u;
    RND(17) RND(29) RND(16) RND(24)
    x0 += KS1;  x1 += KS2 + 4u;
    RND(13) RND(15) RND(26) RND(6)
    x0 += KS2;  x1 += 5u;
#undef RND
    return x0 ^ x1;
}

// Exact path: bit-identical to the reference fp32 computation (accurate logf).
// (f + TINYF == fmaxf(f, tiny) for every representable f in {0} U [2^-23, 1).)
__device__ __forceinline__ float exact_score(const float* __restrict__ erow,
                                             uint32_t row_base, int k) {
    uint32_t bits = threefry_bits(row_base + (uint32_t)k);
    float f = __uint_as_float((bits >> 9) | 0x3f800000u) - 1.0f;  // u in [0,1)
    float u = f + TINYF;
    float g = -logf(-logf(u));
    return __ldg(erow + k) + g;
}

// ---------------------------------------------------------------------------
// One warp per (b, s, p) row. Fast scores via lg2.approx (MUFU pipe):
//   s_j = e_j - ln2 * lg2a(-lg2a(u_j))  ==  (exact_j + const-shift) +- ~2.5e-5
// The uniform per-row shift cancels in all band comparisons. If exactly ONE
// element has s_j >= smax - 4e-4 it is the reference argmax; else (~50 rows
// in 131072) rerun the bit-exact accurate-logf path on the candidate band.
// ---------------------------------------------------------------------------
__global__ void __launch_bounds__(256, 8) symbolic_gumbel_kernel(
    const int*   __restrict__ inputs,       // [B, S] int32
    const float* __restrict__ pattern_map,  // [N_CAT, P, K]
    const float* __restrict__ symbols,      // [K, D]
    float*       __restrict__ out)          // [B, S, P*D]
{
    const int warp = (blockIdx.x * blockDim.x + threadIdx.x) >> 5;
    const int lane = threadIdx.x & 31;

    const int row = warp;                    // grid covers exactly NROWS warps
    const int bs  = row >> 3;
    const int p   = row & 7;
    const int cat = __ldg(&inputs[bs]);

    const float* erow = pattern_map + ((size_t)cat * P_ + p) * K_;
    const uint32_t row_base = (uint32_t)row * (uint32_t)K_;
    const uint32_t base = row_base + (uint32_t)(lane * 8);

    const float4* e4 = reinterpret_cast<const float4*>(erow + lane * 8);
    float4 ea = __ldg(&e4[0]);
    float4 eb = __ldg(&e4[1]);
    float e[8] = {ea.x, ea.y, ea.z, ea.w, eb.x, eb.y, eb.z, eb.w};

    // ---- Pass 1: fast scores ----
    float s[8];
#pragma unroll
    for (int j = 0; j < 8; j++) {
        uint32_t bits = threefry_bits(base + (uint32_t)j);
        float f  = __uint_as_float((bits >> 9) | 0x3f800000u) - 1.0f;  // u in [0,1)
        float u  = f + TINYF;               // == fmaxf(f, tiny), on the fma pipe
        float l1 = lg2a(u);                 // < 0
        float t  = lg2a(-l1);               // neg folds into MUFU src modifier
        s[j] = fmaf(t, -LN2F, e[j]);        // e - ln2*lg2(-lg2 u)
    }

    // Lane-local max (tree) then warp REDUX via monotone uint mapping.
    float m0 = fmaxf(s[0], s[1]), m1 = fmaxf(s[2], s[3]);
    float m2 = fmaxf(s[4], s[5]), m3 = fmaxf(s[6], s[7]);
    float lmax = fmaxf(fmaxf(m0, m1), fmaxf(m2, m3));
    uint32_t ub = __float_as_uint(lmax);
    ub ^= (uint32_t)((int32_t)ub >> 31) | 0x80000000u;     // order-preserving map
    uint32_t um = __reduce_max_sync(FULL, ub);
    um ^= ~(uint32_t)((int32_t)um >> 31) | 0x80000000u;    // inverse map
    const float smax = __uint_as_float(um);

    // ---- Candidate band as a bitmask ----
    const float thr = smax - 4e-4f;
    uint32_t mask = 0;
#pragma unroll
    for (int j = 0; j < 8; j++)
        if (s[j] >= thr) mask |= (1u << j);
    const int tot = __reduce_add_sync(FULL, __popc(mask));

    int bestk;
    if (tot == 1) {
        // Unique candidate == reference argmax (error band is provable).
        unsigned ball = __ballot_sync(FULL, mask != 0);
        int owner = __ffs(ball) - 1;
        int jm = __ffs(mask) - 1;            // valid on owner lane
        bestk = __shfl_sync(FULL, lane * 8 + jm, owner);
    } else {
        // Rare: exact (reference-identical) scores on the candidate band.
        float bestx = NEG_INF;
        bestk = K_;
#pragma unroll
        for (int j = 0; j < 8; j++) {
            bool cand = (mask >> j) & 1u;
            if (__any_sync(FULL, cand)) {
                int   k = lane * 8 + j;
                float x = NEG_INF;
                if (cand) x = exact_score(erow, row_base, k);
                if (x > bestx || (x == bestx && k < bestk)) { bestx = x; bestk = k; }
            }
        }
#pragma unroll
        for (int off = 16; off > 0; off >>= 1) {
            float ob = __shfl_xor_sync(FULL, bestx, off);
            int   ok = __shfl_xor_sync(FULL, bestk, off);
            if (ob > bestx || (ob == bestx && ok < bestk)) { bestx = ob; bestk = ok; }
        }
    }

    // Copy symbols[bestk, :] (64 floats = 256B) to out[row, :], 2 floats/lane
    const float2* srow = reinterpret_cast<const float2*>(symbols + (size_t)bestk * D_);
    float2 val = __ldg(&srow[lane]);
    float2* orow = reinterpret_cast<float2*>(out + (size_t)row * D_);
    orow[lane] = val;
}

extern "C" void kernel_launch(void* const* d_in, const int* in_sizes, int n_in,
                              void* d_out, int out_size) {
    const int*   inputs      = (const int*)  d_in[0];  // [32, 512] int32
    const float* pattern_map = (const float*)d_in[1];  // [50000, 8, 256]
    const float* symbols     = (const float*)d_in[2];  // [256, 64]
    // d_in[3] = tau (== 1.0, positive): argmax invariant; straight-through
    // weights are one-hot to fp32 rounding, so tau is unused.
    float* out = (float*)d_out;                        // [32, 512, 512]

    const int threads = 256;                 // 8 warps -> 8 rows per block
    const int blocks  = NROWS / 8;           // 16384
    symbolic_gumbel_kernel<<<blocks, threads>>>(inputs, pattern_map, symbols, out);
}

// round 15
// speedup vs baseline: 1.1067x; 1.0088x over previous
#include <cuda_runtime.h>
#include <cstdint>

// Problem constants (fixed by the reference)
#define B_ 32
#define S_ 512
#define P_ 8
#define K_ 256
#define D_ 64
#define NROWS (B_ * S_ * P_)   // 131072 rows of K=256 logits each

#define FULL 0xffffffffu
#define NEG_INF __int_as_float(0xff800000)
#define LN2F 0.69314718055994530942f
#define TINYF 1.17549435e-38f

__device__ __forceinline__ uint32_t rotl32(uint32_t x, int r) {
    return __funnelshift_l(x, x, r);
}
__device__ __forceinline__ float lg2a(float x) {
    float r;
    asm("lg2.approx.f32 %0, %1;" : "=f"(r) : "f"(x));
    return r;
}

// ---------------------------------------------------------------------------
// JAX threefry2x32, partitionable mode, key (0, 42); counter = (0, i).
// Draw = x0 ^ x1. ks = (0, 42, 0x1BD11BDA^42). Plain SHF/LOP3/IADD core —
// R5/R8/R11/R12 measured that touching this serial chain loses.
// ---------------------------------------------------------------------------
__device__ __forceinline__ uint32_t threefry_bits(uint32_t i) {
    const uint32_t KS1 = 42u;
    const uint32_t KS2 = 0x1BD11BDAu ^ 42u;
    uint32_t x1 = i + KS1;
    uint32_t x0 = x1;                  // round 1: x0 = 0 + x1
    x1 = rotl32(x1, 13) ^ x0;
#define RND(r) { x0 += x1; x1 = rotl32(x1, (r)) ^ x0; }
    RND(15) RND(26) RND(6)
    x0 += KS1;  x1 += KS2 + 1u;
    RND(17) RND(29) RND(16) RND(24)
    x0 += KS2;  x1 += 2u;              // ks0 = 0
    RND(13) RND(15) RND(26) RND(6)
    /* x0 += ks0 == 0 */ x1 += KS1 + 3u;
    RND(17) RND(29) RND(16) RND(24)
    x0 += KS1;  x1 += KS2 + 4u;
    RND(13) RND(15) RND(26) RND(6)
    x0 += KS2;  x1 += 5u;
#undef RND
    return x0 ^ x1;
}

// Exact path: bit-identical to the reference fp32 computation (accurate logf).
// (f + TINYF == fmaxf(f, tiny) for every representable f in {0} U [2^-23, 1).)
__device__ __forceinline__ float exact_score(const float* __restrict__ erow,
                                             uint32_t row_base, int k) {
    uint32_t bits = threefry_bits(row_base + (uint32_t)k);
    float f = __uint_as_float((bits >> 9) | 0x3f800000u) - 1.0f;  // u in [0,1)
    float u = f + TINYF;
    float g = -logf(-logf(u));
    return __ldg(erow + k) + g;
}

// Fast screen for one row-half: s_j = e_j - ln2 * lg2a(-lg2a(u_j))
__device__ __forceinline__ void screen8(float* s, uint32_t base,
                                        float4 e0, float4 e1) {
    float e[8] = {e0.x, e0.y, e0.z, e0.w, e1.x, e1.y, e1.z, e1.w};
#pragma unroll
    for (int j = 0; j < 8; j++) {
        uint32_t bits = threefry_bits(base + (uint32_t)j);
        float f  = __uint_as_float((bits >> 9) | 0x3f800000u) - 1.0f;
        float u  = f + TINYF;
        float l1 = lg2a(u);
        float t  = lg2a(-l1);
        s[j] = fmaf(t, -LN2F, e[j]);
    }
}

// Warp max of lane-tree max, via REDUX on order-preserving uint map.
__device__ __forceinline__ float warp_smax(const float* s) {
    float m0 = fmaxf(s[0], s[1]), m1 = fmaxf(s[2], s[3]);
    float m2 = fmaxf(s[4], s[5]), m3 = fmaxf(s[6], s[7]);
    float lmax = fmaxf(fmaxf(m0, m1), fmaxf(m2, m3));
    uint32_t ub = __float_as_uint(lmax);
    ub ^= (uint32_t)((int32_t)ub >> 31) | 0x80000000u;
    uint32_t um = __reduce_max_sync(FULL, ub);
    um ^= ~(uint32_t)((int32_t)um >> 31) | 0x80000000u;
    return __uint_as_float(um);
}

// Band + unique test + (rare) bit-exact fallback. Returns argmax index.
__device__ __forceinline__ int resolve(const float* s, float smax, int lane,
                                       const float* __restrict__ erow,
                                       uint32_t row_base) {
    const float thr = smax - 4e-4f;
    uint32_t mask = 0;
#pragma unroll
    for (int j = 0; j < 8; j++)
        if (s[j] >= thr) mask |= (1u << j);
    const int tot = __reduce_add_sync(FULL, __popc(mask));

    int bestk;
    if (tot == 1) {
        unsigned ball = __ballot_sync(FULL, mask != 0);
        int owner = __ffs(ball) - 1;
        int jm = __ffs(mask) - 1;            // valid on owner lane
        bestk = __shfl_sync(FULL, lane * 8 + jm, owner);
    } else {
        // Rare (~50/131072 rows): exact (reference-identical) scores on band.
        float bestx = NEG_INF;
        bestk = K_;
#pragma unroll
        for (int j = 0; j < 8; j++) {
            bool cand = (mask >> j) & 1u;
            if (__any_sync(FULL, cand)) {
                int   k = lane * 8 + j;
                float x = NEG_INF;
                if (cand) x = exact_score(erow, row_base, k);
                if (x > bestx || (x == bestx && k < bestk)) { bestx = x; bestk = k; }
            }
        }
#pragma unroll
        for (int off = 16; off > 0; off >>= 1) {
            float ob = __shfl_xor_sync(FULL, bestx, off);
            int   ok = __shfl_xor_sync(FULL, bestk, off);
            if (ob > bestx || (ob == bestx && ok < bestk)) { bestx = ob; bestk = ok; }
        }
    }
    return bestk;
}

// ---------------------------------------------------------------------------
// TWO rows per warp (2w, 2w+1): same bs (one cat load, adjacent erows), and
// the serial per-row tails are software-pipelined: REDUX-A hides under hash-B,
// the symbols-LDG-A latency hides under REDUX-B + band-B. Halves the
// correlated tail bubbles that capped issue at ~78%.
// ---------------------------------------------------------------------------
__global__ void __launch_bounds__(256, 6) symbolic_gumbel_kernel(
    const int*   __restrict__ inputs,       // [B, S] int32
    const float* __restrict__ pattern_map,  // [N_CAT, P, K]
    const float* __restrict__ symbols,      // [K, D]
    float*       __restrict__ out)          // [B, S, P*D]
{
    const int warp = (blockIdx.x * blockDim.x + threadIdx.x) >> 5;
    const int lane = threadIdx.x & 31;

    const int rowA = warp * 2;               // even -> pA in {0,2,4,6}
    const int bs   = rowA >> 3;
    const int pA   = rowA & 7;
    const int cat  = __ldg(&inputs[bs]);     // shared by rows A and B

    const float* erowA = pattern_map + ((size_t)cat * P_ + pA) * K_;
    const float* erowB = erowA + K_;         // pB = pA + 1, same bs
    const uint32_t baseA = (uint32_t)rowA * (uint32_t)K_ + (uint32_t)(lane * 8);
    const uint32_t baseB = baseA + (uint32_t)K_;
    const uint32_t rbA = (uint32_t)rowA * (uint32_t)K_;
    const uint32_t rbB = rbA + (uint32_t)K_;

    // Issue all energy loads upfront (independent; latency overlaps hash A).
    const float4* eA4 = reinterpret_cast<const float4*>(erowA + lane * 8);
    const float4* eB4 = reinterpret_cast<const float4*>(erowB + lane * 8);
    float4 a0 = __ldg(&eA4[0]);
    float4 a1 = __ldg(&eA4[1]);
    float4 b0 = __ldg(&eB4[0]);
    float4 b1 = __ldg(&eB4[1]);

    // ---- Row A screen ----
    float sA[8];
    screen8(sA, baseA, a0, a1);

    // REDUX A issues; its latency hides under the start of hash B.
    const float smaxA = warp_smax(sA);

    // ---- Row B screen (dense alu stream covers REDUX-A / tail-A latency) ----
    float sB[8];
    screen8(sB, baseB, b0, b1);

    // ---- Resolve A, start its output load ----
    const int bestkA = resolve(sA, smaxA, lane, erowA, rbA);
    const float2* srowA = reinterpret_cast<const float2*>(symbols + (size_t)bestkA * D_);
    float2 valA = __ldg(&srowA[lane]);       // LDG in flight...

    // ...covered by REDUX B:
    const float smaxB = warp_smax(sB);

    // Store A (waits on its LDG), then resolve + output B.
    float2* orowA = reinterpret_cast<float2*>(out + (size_t)rowA * D_);
    orowA[lane] = valA;

    const int bestkB = resolve(sB, smaxB, lane, erowB, rbB);
    const float2* srowB = reinterpret_cast<const float2*>(symbols + (size_t)bestkB * D_);
    float2 valB = __ldg(&srowB[lane]);
    float2* orowB = reinterpret_cast<float2*>(out + (size_t)(rowA + 1) * D_);
    orowB[lane] = valB;
}

extern "C" void kernel_launch(void* const* d_in, const int* in_sizes, int n_in,
                              void* d_out, int out_size) {
    const int*   inputs      = (const int*)  d_in[0];  // [32, 512] int32
    const float* pattern_map = (const float*)d_in[1];  // [50000, 8, 256]
    const float* symbols     = (const float*)d_in[2];  // [256, 64]
    // d_in[3] = tau (== 1.0, positive): argmax invariant; straight-through
    // weights are one-hot to fp32 rounding, so tau is unused.
    float* out = (float*)d_out;                        // [32, 512, 512]

    const int threads = 256;                 // 8 warps -> 16 rows per block
    const int blocks  = NROWS / 16;          // 8192
    symbolic_gumbel_kernel<<<blocks, threads>>>(inputs, pattern_map, symbols, out);
}